// round 1
// baseline (speedup 1.0000x reference)
#include <cuda_runtime.h>
#include <math.h>

#define NN 50000
#define EE 1600000
#define GG 64
#define NODE_IN 32
#define HID 64
#define EDGE_IN 16
#define NLAYER 3

// ---------------- device scratch (static globals; no runtime alloc) ----------------
__device__ float d_h[NN * HID];
__device__ float d_qn[NN * HID];
__device__ float d_kn[NN * HID];
__device__ float d_vn[NN * HID];
__device__ float d_sn[NN * HID];
__device__ int   d_deg[NN];
__device__ int   d_offs[NN + 1];
__device__ int   d_cursor[NN];
__device__ int   d_bsum[64];
__device__ int   d_ssrc[EE];
__device__ int   d_seid[EE];
__device__ float d_sea[(size_t)EE * EDGE_IN];
__device__ float d_pool[GG * HID];
__device__ float d_cnt[GG];

// ---------------- helpers ----------------
__device__ __forceinline__ float red16(float v) {
    v += __shfl_xor_sync(0xffffffffu, v, 8, 16);
    v += __shfl_xor_sync(0xffffffffu, v, 4, 16);
    v += __shfl_xor_sync(0xffffffffu, v, 2, 16);
    v += __shfl_xor_sync(0xffffffffu, v, 1, 16);
    return v;
}

// ---------------- preprocessing: counting sort of edges by dst ----------------
__global__ void zero_deg_kernel() {
    int i = blockIdx.x * blockDim.x + threadIdx.x;
    if (i < NN) d_deg[i] = 0;
}

__global__ void hist_kernel(const int* __restrict__ ei) {
    int e = blockIdx.x * blockDim.x + threadIdx.x;
    if (e < EE) atomicAdd(&d_deg[ei[EE + e]], 1);
}

__global__ void scan1_kernel() {
    __shared__ int s[1024];
    int t = threadIdx.x;
    int i = blockIdx.x * 1024 + t;
    int v = (i < NN) ? d_deg[i] : 0;
    s[t] = v;
    __syncthreads();
    for (int o = 1; o < 1024; o <<= 1) {
        int x = (t >= o) ? s[t - o] : 0;
        __syncthreads();
        s[t] += x;
        __syncthreads();
    }
    if (i < NN) d_offs[i] = s[t] - v;     // exclusive within block
    if (t == 1023) d_bsum[blockIdx.x] = s[t];
}

__global__ void scan2_kernel(int nb) {
    if (threadIdx.x == 0 && blockIdx.x == 0) {
        int run = 0;
        for (int b = 0; b < nb; b++) { int tmp = d_bsum[b]; d_bsum[b] = run; run += tmp; }
        d_offs[NN] = run;  // == EE
    }
}

__global__ void scan3_kernel() {
    int i = blockIdx.x * blockDim.x + threadIdx.x;
    if (i < NN) {
        int v = d_offs[i] + d_bsum[i >> 10];
        d_offs[i] = v;
        d_cursor[i] = v;
    }
}

__global__ void scatter_kernel(const int* __restrict__ ei) {
    int e = blockIdx.x * blockDim.x + threadIdx.x;
    if (e < EE) {
        int dstv = ei[EE + e];
        int pos = atomicAdd(&d_cursor[dstv], 1);
        d_ssrc[pos] = ei[e];
        d_seid[pos] = e;
    }
}

__global__ void permute_ea_kernel(const float* __restrict__ ea) {
    long long t = (long long)blockIdx.x * blockDim.x + threadIdx.x;
    long long total = (long long)EE * 4;
    long long stride = (long long)gridDim.x * blockDim.x;
    for (; t < total; t += stride) {
        int pos = (int)(t >> 2);
        int u = (int)(t & 3);
        int eid = d_seid[pos];
        float4 v = reinterpret_cast<const float4*>(ea)[(size_t)eid * 4 + u];
        reinterpret_cast<float4*>(d_sea)[(size_t)pos * 4 + u] = v;
    }
}

// ---------------- input embedding: h = relu(x @ Wn + bn) ----------------
__global__ __launch_bounds__(256) void node_in_kernel(const float* __restrict__ x,
                                                      const float* __restrict__ Wn,
                                                      const float* __restrict__ bn) {
    __shared__ float Wns[NODE_IN * HID];
    __shared__ float bns[HID];
    __shared__ float xs[4][NODE_IN];
    int t = threadIdx.x;
    for (int u = t; u < NODE_IN * HID; u += 256) Wns[u] = Wn[u];
    if (t < HID) bns[t] = bn[t];
    int j = t & 63, y = t >> 6;
    int node = blockIdx.x * 4 + y;
    if (j < NODE_IN && node < NN) xs[y][j] = x[node * NODE_IN + j];
    __syncthreads();
    if (node < NN) {
        float a = bns[j];
        #pragma unroll
        for (int k = 0; k < NODE_IN; k++) a += xs[y][k] * Wns[k * HID + j];
        d_h[(size_t)node * HID + j] = fmaxf(a, 0.f);
    }
}

// ---------------- fused Q/K/V/Skip node GEMM (register tiled, 64x256 tile) --------
__global__ __launch_bounds__(256) void qkvs_kernel(
    const float* __restrict__ Wq, const float* __restrict__ bq,
    const float* __restrict__ Wk, const float* __restrict__ bk,
    const float* __restrict__ Wv, const float* __restrict__ bv,
    const float* __restrict__ Ws, const float* __restrict__ bs, int layer) {
    extern __shared__ float sm[];
    float* hs = sm;            // 64 x 64
    float* ws = sm + 64 * 64;  // 64 x 256 (Q|K|V|S concatenated along columns)
    const float* Wm[4] = {Wq + layer * HID * HID, Wk + layer * HID * HID,
                          Wv + layer * HID * HID, Ws + layer * HID * HID};
    const float* bm[4] = {bq + layer * HID, bk + layer * HID, bv + layer * HID, bs + layer * HID};
    float* outp[4] = {d_qn, d_kn, d_vn, d_sn};
    int t = threadIdx.x;
    int node0 = blockIdx.x * 64;

    // load weights: 16384 floats = 4096 float4, coalesced
    #pragma unroll
    for (int u = 0; u < 16; u++) {
        int f4 = u * 256 + t;
        int e0 = f4 * 4;
        int k = e0 >> 8;
        int j = e0 & 255;
        int mat = j >> 6, jj = j & 63;
        float4 w4 = *reinterpret_cast<const float4*>(Wm[mat] + k * HID + jj);
        *reinterpret_cast<float4*>(ws + k * 256 + j) = w4;
    }
    // load h tile: 4096 floats = 1024 float4
    #pragma unroll
    for (int u = 0; u < 4; u++) {
        int f4 = u * 256 + t;
        int e0 = f4 * 4;
        int row = e0 >> 6, k = e0 & 63;
        int node = node0 + row;
        float4 h4 = make_float4(0.f, 0.f, 0.f, 0.f);
        if (node < NN) h4 = *reinterpret_cast<const float4*>(d_h + (size_t)node * HID + k);
        *reinterpret_cast<float4*>(hs + e0) = h4;
    }
    __syncthreads();

    int ry = t >> 5;   // warp id: rows ry*8 .. ry*8+7
    int cx = t & 31;   // cols cx + c*32, c = 0..7
    float acc[8][8];
    #pragma unroll
    for (int c = 0; c < 8; c++) {
        int j = cx + c * 32;
        int mat = j >> 6, jj = j & 63;
        float b = bm[mat][jj];
        #pragma unroll
        for (int rr = 0; rr < 8; rr++) acc[rr][c] = b;
    }
    #pragma unroll 8
    for (int k = 0; k < 64; k++) {
        float hr[8], wr[8];
        #pragma unroll
        for (int rr = 0; rr < 8; rr++) hr[rr] = hs[(ry * 8 + rr) * 64 + k];
        #pragma unroll
        for (int c = 0; c < 8; c++) wr[c] = ws[k * 256 + cx + c * 32];
        #pragma unroll
        for (int rr = 0; rr < 8; rr++)
            #pragma unroll
            for (int c = 0; c < 8; c++) acc[rr][c] += hr[rr] * wr[c];
    }
    #pragma unroll
    for (int rr = 0; rr < 8; rr++) {
        int node = node0 + ry * 8 + rr;
        if (node >= NN) continue;
        #pragma unroll
        for (int c = 0; c < 8; c++) {
            int j = cx + c * 32;
            int mat = j >> 6, jj = j & 63;
            outp[mat][(size_t)node * HID + jj] = acc[rr][c];
        }
    }
}

// ---------------- fused attention + softmax + aggregate + skip + residual --------
// One warp per destination node, edges pre-sorted by dst (CSR). Online softmax.
// Edge embedding handled algebraically:
//   q.(k+e) = q.k + ea . (We q^T)   -> precompute qw per node
//   sum attn*(v+e) = sum attn*v + We^T (sum attn*ea)  -> eacc epilogue
__global__ __launch_bounds__(256) void attn_kernel(const float* __restrict__ We, int layer) {
    __shared__ float WeS[EDGE_IN * HID];
    int t = threadIdx.x;
    const float* Wel = We + layer * EDGE_IN * HID;
    for (int u = t; u < EDGE_IN * HID; u += 256) WeS[u] = Wel[u];
    __syncthreads();
    int lane = t & 31;
    int warp = t >> 5;
    int n = blockIdx.x * 8 + warp;
    if (n >= NN) return;
    int r = lane & 15;
    int segbase = lane & 16;   // head segment base: lanes 0-15 -> 0, 16-31 -> 16
    size_t nb = (size_t)n * HID;
    float q0 = d_qn[nb + lane], q1 = d_qn[nb + lane + 32];

    // qw[h(lane), r(lane)] = sum_c q[h*16+c] * We[r][h*16+c]   (reg0: heads 0/1, reg1: heads 2/3)
    float qw0 = 0.f, qw1 = 0.f;
    #pragma unroll
    for (int c0 = 0; c0 < 16; c0++) {
        float qa = __shfl_sync(0xffffffffu, q0, c0, 16);
        float qb = __shfl_sync(0xffffffffu, q1, c0, 16);
        qw0 += qa * WeS[r * HID + segbase + c0];
        qw1 += qb * WeS[r * HID + 32 + segbase + c0];
    }

    float m0 = -1e30f, m1 = -1e30f;
    float den0 = 0.f, den1 = 0.f;
    float acc0 = 0.f, acc1 = 0.f;
    float eac0 = 0.f, eac1 = 0.f;
    int beg = d_offs[n], end = d_offs[n + 1];
    for (int i = beg; i < end; i++) {
        int src = d_ssrc[i];
        float eav = d_sea[(size_t)i * EDGE_IN + r];
        const float* kp = d_kn + (size_t)src * HID;
        const float* vp = d_vn + (size_t)src * HID;
        float k0 = kp[lane], k1 = kp[lane + 32];
        float v0 = vp[lane], v1 = vp[lane + 32];
        float p0 = q0 * k0 + eav * qw0;
        float p1 = q1 * k1 + eav * qw1;
        p0 = red16(p0) * 0.25f;   // 1/sqrt(C), C=16
        p1 = red16(p1) * 0.25f;
        // online softmax, head group 0 (reg0)
        float mn0 = fmaxf(m0, p0);
        float sc0 = __expf(m0 - mn0);
        float w0 = __expf(p0 - mn0);
        den0 = den0 * sc0 + w0;
        acc0 = acc0 * sc0 + w0 * v0;
        eac0 = eac0 * sc0 + w0 * eav;
        m0 = mn0;
        // head group 1 (reg1)
        float mn1 = fmaxf(m1, p1);
        float sc1 = __expf(m1 - mn1);
        float w1 = __expf(p1 - mn1);
        den1 = den1 * sc1 + w1;
        acc1 = acc1 * sc1 + w1 * v1;
        eac1 = eac1 * sc1 + w1 * eav;
        m1 = mn1;
    }
    // epilogue: add We^T * eacc (per head), once per node
    #pragma unroll
    for (int rr = 0; rr < 16; rr++) {
        float e0 = __shfl_sync(0xffffffffu, eac0, rr, 16);
        float e1 = __shfl_sync(0xffffffffu, eac1, rr, 16);
        acc0 += WeS[rr * HID + lane] * e0;
        acc1 += WeS[rr * HID + lane + 32] * e1;
    }
    float o0 = acc0 / (den0 + 1e-16f);
    float o1 = acc1 / (den1 + 1e-16f);
    float s0 = d_sn[nb + lane], s1 = d_sn[nb + lane + 32];
    d_h[nb + lane]      += fmaxf(o0 + s0, 0.f);
    d_h[nb + lane + 32] += fmaxf(o1 + s1, 0.f);
}

// ---------------- pooling + readout MLP ----------------
__global__ void zero_pool_kernel() {
    int i = blockIdx.x * blockDim.x + threadIdx.x;
    if (i < GG * HID) d_pool[i] = 0.f;
    if (i < GG) d_cnt[i] = 0.f;
}

__global__ void pool_acc_kernel(const int* __restrict__ batch) {
    int t = blockIdx.x * blockDim.x + threadIdx.x;
    if (t < NN * HID) {
        int node = t >> 6;
        int c = t & 63;
        int g = batch[node];
        atomicAdd(&d_pool[g * HID + c], d_h[t]);
        if (c == 0) atomicAdd(&d_cnt[g], 1.f);
    }
}

__global__ void final_kernel(const float* __restrict__ W1, const float* __restrict__ b1,
                             const float* __restrict__ W2, const float* __restrict__ b2,
                             float* __restrict__ out) {
    int g = threadIdx.x;
    if (g >= GG) return;
    float inv = 1.f / fmaxf(d_cnt[g], 1.f);
    float p[HID];
    #pragma unroll
    for (int k = 0; k < HID; k++) p[k] = d_pool[g * HID + k] * inv;
    float o = b2[0];
    #pragma unroll
    for (int j = 0; j < HID / 2; j++) {
        float a = b1[j];
        #pragma unroll
        for (int k = 0; k < HID; k++) a += p[k] * W1[k * (HID / 2) + j];
        o += fmaxf(a, 0.f) * W2[j];
    }
    out[g] = o;
}

// ---------------- launch ----------------
extern "C" void kernel_launch(void* const* d_in, const int* in_sizes, int n_in,
                              void* d_out, int out_size) {
    const float* x   = (const float*)d_in[0];
    const int*   ei  = (const int*)d_in[1];
    const float* ea  = (const float*)d_in[2];
    const int*   bat = (const int*)d_in[3];
    const float* Wn  = (const float*)d_in[4];
    const float* bn  = (const float*)d_in[5];
    const float* Wq  = (const float*)d_in[6];
    const float* bq  = (const float*)d_in[7];
    const float* Wk  = (const float*)d_in[8];
    const float* bk  = (const float*)d_in[9];
    const float* Wv  = (const float*)d_in[10];
    const float* bv  = (const float*)d_in[11];
    const float* We  = (const float*)d_in[12];
    const float* Ws  = (const float*)d_in[13];
    const float* bs  = (const float*)d_in[14];
    const float* W1  = (const float*)d_in[15];
    const float* b1  = (const float*)d_in[16];
    const float* W2  = (const float*)d_in[17];
    const float* b2  = (const float*)d_in[18];
    float* out = (float*)d_out;

    cudaFuncSetAttribute(qkvs_kernel, cudaFuncAttributeMaxDynamicSharedMemorySize, 96 * 1024);

    // 1) sort edges by dst (counting sort -> CSR), permute edge_attr
    zero_deg_kernel<<<(NN + 255) / 256, 256>>>();
    hist_kernel<<<(EE + 255) / 256, 256>>>(ei);
    int nb = (NN + 1023) / 1024;
    scan1_kernel<<<nb, 1024>>>();
    scan2_kernel<<<1, 32>>>(nb);
    scan3_kernel<<<(NN + 255) / 256, 256>>>();
    scatter_kernel<<<(EE + 255) / 256, 256>>>(ei);
    permute_ea_kernel<<<25000, 256>>>(ea);

    // 2) input embedding
    node_in_kernel<<<(NN + 3) / 4, 256>>>(x, Wn, bn);

    // 3) transformer conv layers
    for (int l = 0; l < NLAYER; l++) {
        qkvs_kernel<<<(NN + 63) / 64, 256, 80 * 1024>>>(Wq, bq, Wk, bk, Wv, bv, Ws, bs, l);
        attn_kernel<<<(NN + 7) / 8, 256>>>(We, l);
    }

    // 4) mean pool + MLP head
    zero_pool_kernel<<<(GG * HID + 255) / 256, 256>>>();
    pool_acc_kernel<<<(NN * HID + 255) / 256, 256>>>(bat);
    final_kernel<<<1, 64>>>(W1, b1, W2, b2, out);
}

// round 3
// speedup vs baseline: 1.4024x; 1.4024x over previous
#include <cuda_runtime.h>
#include <math.h>

#define NN 50000
#define EE 1600000
#define GG 64
#define NODE_IN 32
#define HID 64
#define EDGE_IN 16
#define NLAYER 3

// ---------------- device scratch (static globals; no runtime alloc) ----------------
__device__ float d_h[NN * HID];
__device__ float d_qn[NN * HID];
__device__ float d_kn[NN * HID];
__device__ float d_vn[NN * HID];
__device__ float d_sn[NN * HID];
__device__ float d_qwn[NN * HID];   // per-node q.We projection (4 heads x 16 r, packed)
__device__ int   d_deg[NN];
__device__ int   d_offs[NN + 1];
__device__ int   d_cursor[NN];
__device__ int   d_bsum[64];
__device__ int2  d_sedge[EE];       // {src, eid} sorted by dst
__device__ float d_M[HID * HID];    // fused Wq x We matrix for qw GEMM
__device__ float d_bqw[HID];

__device__ __forceinline__ float ex2(float x) {
    float r;
    asm("ex2.approx.f32 %0, %1;" : "=f"(r) : "f"(x));
    return r;
}

// ---------------- preprocessing: counting sort of edges by dst ----------------
__global__ void zero_deg_kernel() {
    int i = blockIdx.x * blockDim.x + threadIdx.x;
    if (i < NN) d_deg[i] = 0;
}

__global__ void hist_kernel(const int* __restrict__ ei) {
    int e = blockIdx.x * blockDim.x + threadIdx.x;
    if (e < EE) atomicAdd(&d_deg[ei[EE + e]], 1);
}

__global__ void scan1_kernel() {
    __shared__ int s[1024];
    int t = threadIdx.x;
    int i = blockIdx.x * 1024 + t;
    int v = (i < NN) ? d_deg[i] : 0;
    s[t] = v;
    __syncthreads();
    for (int o = 1; o < 1024; o <<= 1) {
        int x = (t >= o) ? s[t - o] : 0;
        __syncthreads();
        s[t] += x;
        __syncthreads();
    }
    if (i < NN) d_offs[i] = s[t] - v;
    if (t == 1023) d_bsum[blockIdx.x] = s[t];
}

__global__ void scan2_kernel(int nb) {
    if (threadIdx.x == 0 && blockIdx.x == 0) {
        int run = 0;
        for (int b = 0; b < nb; b++) { int tmp = d_bsum[b]; d_bsum[b] = run; run += tmp; }
        d_offs[NN] = run;
    }
}

__global__ void scan3_kernel() {
    int i = blockIdx.x * blockDim.x + threadIdx.x;
    if (i < NN) {
        int v = d_offs[i] + d_bsum[i >> 10];
        d_offs[i] = v;
        d_cursor[i] = v;
    }
}

__global__ void scatter_kernel(const int* __restrict__ ei) {
    int e = blockIdx.x * blockDim.x + threadIdx.x;
    if (e < EE) {
        int dstv = ei[EE + e];
        int pos = atomicAdd(&d_cursor[dstv], 1);
        d_sedge[pos] = make_int2(ei[e], e);
    }
}

// ---------------- input embedding: h = relu(x @ Wn + bn) ----------------
__global__ __launch_bounds__(256) void node_in_kernel(const float* __restrict__ x,
                                                      const float* __restrict__ Wn,
                                                      const float* __restrict__ bn) {
    __shared__ float Wns[NODE_IN * HID];
    __shared__ float bns[HID];
    __shared__ float xs[4][NODE_IN];
    int t = threadIdx.x;
    for (int u = t; u < NODE_IN * HID; u += 256) Wns[u] = Wn[u];
    if (t < HID) bns[t] = bn[t];
    int j = t & 63, y = t >> 6;
    int node = blockIdx.x * 4 + y;
    if (j < NODE_IN && node < NN) xs[y][j] = x[node * NODE_IN + j];
    __syncthreads();
    if (node < NN) {
        float a = bns[j];
        #pragma unroll
        for (int k = 0; k < NODE_IN; k++) a += xs[y][k] * Wns[k * HID + j];
        d_h[(size_t)node * HID + j] = fmaxf(a, 0.f);
    }
}

// ---------------- per-layer M = per-head (Wq x We), bqw = per-head (bq x We) ------
__global__ void prep_M_kernel(const float* __restrict__ Wq, const float* __restrict__ bq,
                              const float* __restrict__ We, int layer) {
    int idx = blockIdx.x * 256 + threadIdx.x;
    const float* Wql = Wq + layer * HID * HID;
    const float* Wel = We + layer * EDGE_IN * HID;
    if (idx < HID * HID) {
        int krow = idx >> 6, col = idx & 63;
        int h = col >> 4, r = col & 15;
        float s = 0.f;
        #pragma unroll
        for (int c = 0; c < 16; c++)
            s += Wql[krow * HID + h * 16 + c] * Wel[r * HID + h * 16 + c];
        d_M[idx] = s;
    }
    if (idx < HID) {
        int h = idx >> 4, r = idx & 15;
        const float* bql = bq + layer * HID;
        float s = 0.f;
        #pragma unroll
        for (int c = 0; c < 16; c++)
            s += bql[h * 16 + c] * Wel[r * HID + h * 16 + c];
        d_bqw[idx] = s;
    }
}

// ---------------- fused Q/K/V/Skip/QW node GEMM (64 x 320 tile) -------------------
__global__ __launch_bounds__(256, 2) void qkvs_kernel(
    const float* __restrict__ Wq, const float* __restrict__ bq,
    const float* __restrict__ Wk, const float* __restrict__ bk,
    const float* __restrict__ Wv, const float* __restrict__ bv,
    const float* __restrict__ Ws, const float* __restrict__ bs, int layer) {
    extern __shared__ float sm[];
    float* hs = sm;            // 64 x 64
    float* ws = sm + 64 * 64;  // 64 x 320
    const float* Wm[5] = {Wq + layer * HID * HID, Wk + layer * HID * HID,
                          Wv + layer * HID * HID, Ws + layer * HID * HID, d_M};
    const float* bm[5] = {bq + layer * HID, bk + layer * HID, bv + layer * HID,
                          bs + layer * HID, d_bqw};
    float* outp[5] = {d_qn, d_kn, d_vn, d_sn, d_qwn};
    int t = threadIdx.x;
    int node0 = blockIdx.x * 64;

    #pragma unroll
    for (int u = 0; u < 20; u++) {
        int mat = u >> 2;
        int e0 = ((u & 3) * 256 + t) * 4;
        int k = e0 >> 6, jj = e0 & 63;
        float4 w4 = *reinterpret_cast<const float4*>(Wm[mat] + k * HID + jj);
        *reinterpret_cast<float4*>(ws + k * 320 + mat * 64 + jj) = w4;
    }
    #pragma unroll
    for (int u = 0; u < 4; u++) {
        int e0 = (u * 256 + t) * 4;
        int row = e0 >> 6, k = e0 & 63;
        int node = node0 + row;
        float4 h4 = make_float4(0.f, 0.f, 0.f, 0.f);
        if (node < NN) h4 = *reinterpret_cast<const float4*>(d_h + (size_t)node * HID + k);
        *reinterpret_cast<float4*>(hs + e0) = h4;
    }
    __syncthreads();

    int ry = t >> 5;
    int cx = t & 31;
    float acc[8][10];
    #pragma unroll
    for (int c = 0; c < 10; c++) {
        int mat = c >> 1;
        int jj = (c & 1) * 32 + cx;
        float b = bm[mat][jj];
        #pragma unroll
        for (int rr = 0; rr < 8; rr++) acc[rr][c] = b;
    }
    #pragma unroll 4
    for (int k0 = 0; k0 < 64; k0 += 4) {
        float4 hr4[8];
        #pragma unroll
        for (int rr = 0; rr < 8; rr++)
            hr4[rr] = *reinterpret_cast<const float4*>(hs + (ry * 8 + rr) * 64 + k0);
        #pragma unroll
        for (int kk = 0; kk < 4; kk++) {
            float wr[10];
            #pragma unroll
            for (int c = 0; c < 10; c++) wr[c] = ws[(k0 + kk) * 320 + cx + c * 32];
            #pragma unroll
            for (int rr = 0; rr < 8; rr++) {
                float hv = (kk == 0) ? hr4[rr].x : (kk == 1) ? hr4[rr].y
                         : (kk == 2) ? hr4[rr].z : hr4[rr].w;
                #pragma unroll
                for (int c = 0; c < 10; c++) acc[rr][c] += hv * wr[c];
            }
        }
    }
    #pragma unroll
    for (int rr = 0; rr < 8; rr++) {
        int node = node0 + ry * 8 + rr;
        if (node >= NN) continue;
        #pragma unroll
        for (int c = 0; c < 10; c++) {
            int mat = c >> 1;
            int jj = (c & 1) * 32 + cx;
            outp[mat][(size_t)node * HID + jj] = acc[rr][c];
        }
    }
}

// ---------------- fused attention: half-warp per edge, warp per node -------------
// lane = 16*hf + 4*head + p ; lane owns channels (4h+p)*4..+3, edge-feats p*4..+3.
// Two parallel softmax streams (one per half), merged at the end.
// UNIFORM trip count across the warp: both streams run ceil(d/2) iterations; the
// trailing invalid slot (odd d, stream 1) clamps its load and contributes w=0.
__global__ __launch_bounds__(256) void attn_kernel(const float* __restrict__ We,
                                                   const float* __restrict__ ea,
                                                   int layer) {
    __shared__ float WeS[16 * 68 + 4];  // skewed: [r*68 + col + (col>>4)]
    int t = threadIdx.x;
    const float* Wel = We + layer * EDGE_IN * HID;
    for (int u = t; u < EDGE_IN * HID; u += 256) {
        int r = u >> 6, col = u & 63;
        WeS[r * 68 + col + (col >> 4)] = Wel[u];
    }
    __syncthreads();

    int lane = t & 31;
    int warp = t >> 5;
    int n = blockIdx.x * 8 + warp;
    if (n >= NN) return;

    int hf = lane >> 4;
    int hl = lane & 15;
    int h = hl >> 2;
    int p = hl & 3;
    int cbs = hl * 4 + h;

    float4 q  = reinterpret_cast<const float4*>(d_qn)[n * 16 + hl];
    float4 qw = reinterpret_cast<const float4*>(d_qwn)[n * 16 + hl];

    float m = -1e30f, den = 0.f;
    float4 acc = make_float4(0.f, 0.f, 0.f, 0.f);
    float4 eac = make_float4(0.f, 0.f, 0.f, 0.f);

    int beg = d_offs[n], end = d_offs[n + 1];
    int d = end - beg;
    int itmax = (d + 1) >> 1;          // warp-uniform trip count

    int i = beg + hf;
    bool vld = (i < end);
    int2 se; float4 k4, v4, e4;
    if (itmax > 0) {
        int idx = vld ? i : (end - 1);
        se = d_sedge[idx];
        k4 = reinterpret_cast<const float4*>(d_kn)[se.x * 16 + hl];
        v4 = reinterpret_cast<const float4*>(d_vn)[se.x * 16 + hl];
        e4 = reinterpret_cast<const float4*>(ea)[se.y * 4 + p];
    }
    for (int it = 0; it < itmax; it++) {
        float4 ck = k4, cv = v4, ce = e4;
        bool cvld = vld;
        i += 2;
        vld = (i < end);
        if (it + 1 < itmax) {
            int idx = vld ? i : (end - 1);
            se = d_sedge[idx];
            k4 = reinterpret_cast<const float4*>(d_kn)[se.x * 16 + hl];
            v4 = reinterpret_cast<const float4*>(d_vn)[se.x * 16 + hl];
            e4 = reinterpret_cast<const float4*>(ea)[se.y * 4 + p];
        }
        float pp = q.x * ck.x + q.y * ck.y + q.z * ck.z + q.w * ck.w
                 + qw.x * ce.x + qw.y * ce.y + qw.z * ce.z + qw.w * ce.w;
        pp += __shfl_xor_sync(0xffffffffu, pp, 1);
        pp += __shfl_xor_sync(0xffffffffu, pp, 2);
        pp = cvld ? pp * 0.36067376022224085f : -1e30f;   // 0.25*log2(e); -inf if invalid
        float w;
        if (cvld && pp > m) {          // new running max (rare)
            float sc = ex2(m - pp);
            m = pp;
            den *= sc;
            acc.x *= sc; acc.y *= sc; acc.z *= sc; acc.w *= sc;
            eac.x *= sc; eac.y *= sc; eac.z *= sc; eac.w *= sc;
            w = 1.0f;
        } else {
            w = ex2(pp - m);           // invalid: pp-m=0 -> w=1, zeroed below
            w = cvld ? w : 0.f;
        }
        den += w;
        acc.x += w * cv.x; acc.y += w * cv.y; acc.z += w * cv.z; acc.w += w * cv.w;
        eac.x += w * ce.x; eac.y += w * ce.y; eac.z += w * ce.z; eac.w += w * ce.w;
    }

    // fold edge-embedding: acc[c] += sum_r eacc[h][r] * We[r][c]   (conflict-free smem)
    float ea_arr[4] = {eac.x, eac.y, eac.z, eac.w};
    #pragma unroll
    for (int r = 0; r < 16; r++) {
        float ev = __shfl_sync(0xffffffffu, ea_arr[r & 3], (h << 2) + (r >> 2), 16);
        acc.x += ev * WeS[r * 68 + cbs + 0];
        acc.y += ev * WeS[r * 68 + cbs + 1];
        acc.z += ev * WeS[r * 68 + cbs + 2];
        acc.w += ev * WeS[r * 68 + cbs + 3];
    }

    // merge the two half-warp softmax streams
    float om  = __shfl_xor_sync(0xffffffffu, m,    16);
    float odn = __shfl_xor_sync(0xffffffffu, den,  16);
    float oax = __shfl_xor_sync(0xffffffffu, acc.x, 16);
    float oay = __shfl_xor_sync(0xffffffffu, acc.y, 16);
    float oaz = __shfl_xor_sync(0xffffffffu, acc.z, 16);
    float oaw = __shfl_xor_sync(0xffffffffu, acc.w, 16);
    float mm = fmaxf(m, om);
    float sA = ex2(m - mm), sB = ex2(om - mm);
    den = den * sA + odn * sB;
    float ox = acc.x * sA + oax * sB;
    float oy = acc.y * sA + oay * sB;
    float oz = acc.z * sA + oaz * sB;
    float ow = acc.w * sA + oaw * sB;

    if (hf == 0) {
        float inv = 1.f / (den + 1e-16f);
        float4 s4 = reinterpret_cast<const float4*>(d_sn)[n * 16 + hl];
        float4 hc = reinterpret_cast<const float4*>(d_h)[n * 16 + hl];
        hc.x += fmaxf(ox * inv + s4.x, 0.f);
        hc.y += fmaxf(oy * inv + s4.y, 0.f);
        hc.z += fmaxf(oz * inv + s4.z, 0.f);
        hc.w += fmaxf(ow * inv + s4.w, 0.f);
        reinterpret_cast<float4*>(d_h)[n * 16 + hl] = hc;
    }
}

// ---------------- fused mean pool (sorted batch) + readout MLP -------------------
__global__ __launch_bounds__(256) void pool_mlp_kernel(const int* __restrict__ batch,
    const float* __restrict__ W1, const float* __restrict__ b1,
    const float* __restrict__ W2, const float* __restrict__ b2,
    float* __restrict__ out) {
    __shared__ float red[256];
    __shared__ float sp[64];
    __shared__ int bnd[2];
    int g = blockIdx.x, t = threadIdx.x;
    if (t == 0) {
        int lo = 0, hi = NN;
        while (lo < hi) { int mid = (lo + hi) >> 1; if (batch[mid] < g) lo = mid + 1; else hi = mid; }
        bnd[0] = lo;
        int lo2 = lo, hi2 = NN;
        while (lo2 < hi2) { int mid = (lo2 + hi2) >> 1; if (batch[mid] < g + 1) lo2 = mid + 1; else hi2 = mid; }
        bnd[1] = lo2;
    }
    __syncthreads();
    int lo = bnd[0], hi = bnd[1];
    int ch = t & 63, rg = t >> 6;
    float a = 0.f;
    for (int nd = lo + rg; nd < hi; nd += 4) a += d_h[(size_t)nd * HID + ch];
    red[t] = a;
    __syncthreads();
    if (t < 64) {
        float s = red[t] + red[t + 64] + red[t + 128] + red[t + 192];
        sp[t] = s / fmaxf((float)(hi - lo), 1.0f);
    }
    __syncthreads();
    if (t < 32) {
        float accv = b1[t];
        #pragma unroll
        for (int k = 0; k < HID; k++) accv += sp[k] * W1[k * 32 + t];
        float v = fmaxf(accv, 0.f) * W2[t];
        #pragma unroll
        for (int o = 16; o; o >>= 1) v += __shfl_xor_sync(0xffffffffu, v, o);
        if (t == 0) out[g] = v + b2[0];
    }
}

// ---------------- launch ----------------
extern "C" void kernel_launch(void* const* d_in, const int* in_sizes, int n_in,
                              void* d_out, int out_size) {
    const float* x   = (const float*)d_in[0];
    const int*   ei  = (const int*)d_in[1];
    const float* ea  = (const float*)d_in[2];
    const int*   bat = (const int*)d_in[3];
    const float* Wn  = (const float*)d_in[4];
    const float* bn  = (const float*)d_in[5];
    const float* Wq  = (const float*)d_in[6];
    const float* bq  = (const float*)d_in[7];
    const float* Wk  = (const float*)d_in[8];
    const float* bk  = (const float*)d_in[9];
    const float* Wv  = (const float*)d_in[10];
    const float* bv  = (const float*)d_in[11];
    const float* We  = (const float*)d_in[12];
    const float* Ws  = (const float*)d_in[13];
    const float* bs  = (const float*)d_in[14];
    const float* W1  = (const float*)d_in[15];
    const float* b1  = (const float*)d_in[16];
    const float* W2  = (const float*)d_in[17];
    const float* b2  = (const float*)d_in[18];
    float* out = (float*)d_out;

    cudaFuncSetAttribute(qkvs_kernel, cudaFuncAttributeMaxDynamicSharedMemorySize, 100 * 1024);

    // 1) counting sort of edges by dst -> CSR of {src, eid}
    zero_deg_kernel<<<(NN + 255) / 256, 256>>>();
    hist_kernel<<<(EE + 255) / 256, 256>>>(ei);
    int nb = (NN + 1023) / 1024;
    scan1_kernel<<<nb, 1024>>>();
    scan2_kernel<<<1, 32>>>(nb);
    scan3_kernel<<<(NN + 255) / 256, 256>>>();
    scatter_kernel<<<(EE + 255) / 256, 256>>>(ei);

    // 2) input embedding
    node_in_kernel<<<(NN + 3) / 4, 256>>>(x, Wn, bn);

    // 3) transformer conv layers
    for (int l = 0; l < NLAYER; l++) {
        prep_M_kernel<<<16, 256>>>(Wq, bq, We, l);
        qkvs_kernel<<<(NN + 63) / 64, 256, (64 * 64 + 64 * 320) * 4>>>(
            Wq, bq, Wk, bk, Wv, bv, Ws, bs, l);
        attn_kernel<<<(NN + 7) / 8, 256>>>(We, ea, l);
    }

    // 4) fused mean pool + MLP head (batch is sorted)
    pool_mlp_kernel<<<GG, 256>>>(bat, W1, b1, W2, b2, out);
}